// round 4
// baseline (speedup 1.0000x reference)
#include <cuda_runtime.h>
#include <math.h>

#define BB 4
#define TT 4096
#define DD 32
#define SPLITS 8
#define CHUNK 512      // TT / SPLITS
#define MTILE 128      // query rows per CTA (2 adjacent rows per thread)
#define NKEY 64        // key rows per smem tile

// Scratch (no cudaMalloc allowed)
__device__ float g_q[BB * TT * DD];
__device__ float g_k[BB * TT * DD];
__device__ float g_v[BB * TT * DD];
__device__ float g_po[BB * SPLITS * TT * DD];   // partial o (unnormalized)
__device__ float g_pml[BB * SPLITS * TT * 2];   // partial (m, l)

#define DOT4(qq, kk) (fmaf((qq).x, (kk).x, fmaf((qq).y, (kk).y, fmaf((qq).z, (kk).z, (qq).w * (kk).w))))

// ---------------------------------------------------------------------------
// Kernel 1: QKV projection. W rows in registers (thread -> h = lane),
// x staged in smem. 128 threads = 4 warps x 8 rows; grid = BB*TT/32.
// ---------------------------------------------------------------------------
__global__ void __launch_bounds__(128) qkv_kernel(const float* __restrict__ x,
                                                  const float* __restrict__ Wq,
                                                  const float* __restrict__ Wk,
                                                  const float* __restrict__ Wv) {
    __shared__ float4 xs[32 * 8];   // 32 rows x 32 floats = 4KB
    const int tid = threadIdx.x, lane = tid & 31, warp = tid >> 5;

    float wq[32], wk[32], wv[32];
    {
        const float4* Wq4 = (const float4*)(Wq + lane * DD);
        const float4* Wk4 = (const float4*)(Wk + lane * DD);
        const float4* Wv4 = (const float4*)(Wv + lane * DD);
#pragma unroll
        for (int j = 0; j < 8; j++) {
            ((float4*)wq)[j] = Wq4[j];
            ((float4*)wk)[j] = Wk4[j];
            ((float4*)wv)[j] = Wv4[j];
        }
    }
    const int rowbase = blockIdx.x * 32;
    const float4* xg = (const float4*)(x + rowbase * DD);
#pragma unroll
    for (int idx = tid; idx < 32 * 8; idx += 128) xs[idx] = xg[idx];
    __syncthreads();

#pragma unroll
    for (int rr = 0; rr < 8; rr++) {
        const int row = warp * 8 + rr;
        float aq = 0.f, ak = 0.f, av = 0.f;
#pragma unroll
        for (int j = 0; j < 8; j++) {
            float4 xv = xs[row * 8 + j];
            aq = fmaf(xv.x, wq[4*j],   aq); ak = fmaf(xv.x, wk[4*j],   ak); av = fmaf(xv.x, wv[4*j],   av);
            aq = fmaf(xv.y, wq[4*j+1], aq); ak = fmaf(xv.y, wk[4*j+1], ak); av = fmaf(xv.y, wv[4*j+1], av);
            aq = fmaf(xv.z, wq[4*j+2], aq); ak = fmaf(xv.z, wk[4*j+2], ak); av = fmaf(xv.z, wv[4*j+2], av);
            aq = fmaf(xv.w, wq[4*j+3], aq); ak = fmaf(xv.w, wk[4*j+3], ak); av = fmaf(xv.w, wv[4*j+3], av);
        }
        const int g = (rowbase + row) * DD + lane;
        g_q[g] = aq; g_k[g] = ak; g_v[g] = av;
    }
}

// ---------------------------------------------------------------------------
// Kernel 2: partial flash attention, split-KV, scalar fp32, 2 rows/thread.
// grid = (TT/128, SPLITS, BB); 64 threads; thread -> rows (2*tid, 2*tid+1).
// Each K/V smem row read is amortized over both query rows (halved LDS traffic).
// ---------------------------------------------------------------------------
__global__ void __launch_bounds__(64) attn_partial_kernel() {
    const int i  = blockIdx.x;   // 128-row query tile
    const int sp = blockIdx.y;   // kv split
    const int b  = blockIdx.z;
    if (sp * 4 > i) return;      // chunk entirely above the diagonal

    const int tid = threadIdx.x;
    const int r0 = i * MTILE + 2 * tid;
    const int r1 = r0 + 1;

    __shared__ float4 Ks[NKEY * 8];   // 64 rows x 128B = 8KB
    __shared__ float4 Vs[NKEY * 8];

    const float SCALE = 0.17677669529663687f;   // 32^-0.5
    float4 q0[8], q1[8], o0[8], o1[8];
    {
        const float4* qg = (const float4*)(g_q + (b * TT + r0) * DD);
#pragma unroll
        for (int j = 0; j < 8; j++) {
            float4 t = qg[j];
            t.x *= SCALE; t.y *= SCALE; t.z *= SCALE; t.w *= SCALE;
            q0[j] = t;
        }
#pragma unroll
        for (int j = 0; j < 8; j++) {
            float4 t = qg[8 + j];
            t.x *= SCALE; t.y *= SCALE; t.z *= SCALE; t.w *= SCALE;
            q1[j] = t;
        }
        const float4 z = make_float4(0.f, 0.f, 0.f, 0.f);
#pragma unroll
        for (int j = 0; j < 8; j++) { o0[j] = z; o1[j] = z; }
    }
    float m0 = -INFINITY, l0 = 0.f, m1 = -INFINITY, l1 = 0.f;

    const int nkt = min(CHUNK / NKEY, 2 * i + 2 - 8 * sp);  // causal key tiles
    const float4* Kg = (const float4*)(g_k + (b * TT + sp * CHUNK) * DD);
    const float4* Vg = (const float4*)(g_v + (b * TT + sp * CHUNK) * DD);

    for (int jt = 0; jt < nkt; jt++) {
        if (jt) __syncthreads();
#pragma unroll
        for (int u = 0; u < 8; u++) {
            Ks[tid + 64 * u] = Kg[jt * 512 + tid + 64 * u];
            Vs[tid + 64 * u] = Vg[jt * 512 + tid + 64 * u];
        }
        __syncthreads();

        const int ktbase = sp * CHUNK + jt * NKEY;
        const int lim  = min(NKEY, r1 - ktbase + 1);   // keys valid for row r1
        const int lim0 = min(NKEY, r0 - ktbase + 1);   // keys valid for row r0
        for (int n = 0; n < lim; n++) {
            float4 kk[8];
#pragma unroll
            for (int j = 0; j < 8; j++) kk[j] = Ks[n * 8 + j];

            float sa0 = 0.f, sb0 = 0.f, sa1 = 0.f, sb1 = 0.f;
#pragma unroll
            for (int j = 0; j < 4; j++) {
                sa0 += DOT4(q0[2*j],   kk[2*j]);
                sb0 += DOT4(q0[2*j+1], kk[2*j+1]);
                sa1 += DOT4(q1[2*j],   kk[2*j]);
                sb1 += DOT4(q1[2*j+1], kk[2*j+1]);
            }
            const float sc0 = sa0 + sb0;
            const float sc1 = sa1 + sb1;

            float4 vv[8];
#pragma unroll
            for (int j = 0; j < 8; j++) vv[j] = Vs[n * 8 + j];

            // Reference quirk: tril(wei)==0 -> -inf. Causal + exact-zero check.
            if (n < lim0 && sc0 != 0.0f) {
                if (sc0 > m0) {
                    float c = __expf(m0 - sc0); m0 = sc0; l0 *= c;
#pragma unroll
                    for (int j = 0; j < 8; j++) {
                        o0[j].x *= c; o0[j].y *= c; o0[j].z *= c; o0[j].w *= c;
                    }
                }
                float p = __expf(sc0 - m0); l0 += p;
#pragma unroll
                for (int j = 0; j < 8; j++) {
                    o0[j].x = fmaf(p, vv[j].x, o0[j].x);
                    o0[j].y = fmaf(p, vv[j].y, o0[j].y);
                    o0[j].z = fmaf(p, vv[j].z, o0[j].z);
                    o0[j].w = fmaf(p, vv[j].w, o0[j].w);
                }
            }
            if (sc1 != 0.0f) {   // n < lim guaranteed
                if (sc1 > m1) {
                    float c = __expf(m1 - sc1); m1 = sc1; l1 *= c;
#pragma unroll
                    for (int j = 0; j < 8; j++) {
                        o1[j].x *= c; o1[j].y *= c; o1[j].z *= c; o1[j].w *= c;
                    }
                }
                float p = __expf(sc1 - m1); l1 += p;
#pragma unroll
                for (int j = 0; j < 8; j++) {
                    o1[j].x = fmaf(p, vv[j].x, o1[j].x);
                    o1[j].y = fmaf(p, vv[j].y, o1[j].y);
                    o1[j].z = fmaf(p, vv[j].z, o1[j].z);
                    o1[j].w = fmaf(p, vv[j].w, o1[j].w);
                }
            }
        }
    }

    const int base = (b * SPLITS + sp) * TT;
    g_pml[2*(base + r0)]     = m0;
    g_pml[2*(base + r0) + 1] = l0;
    g_pml[2*(base + r1)]     = m1;
    g_pml[2*(base + r1) + 1] = l1;
    float4* po0 = (float4*)(g_po + (base + r0) * DD);
    float4* po1 = (float4*)(g_po + (base + r1) * DD);
#pragma unroll
    for (int j = 0; j < 8; j++) po0[j] = o0[j];
#pragma unroll
    for (int j = 0; j < 8; j++) po1[j] = o1[j];
}

// ---------------------------------------------------------------------------
// Kernel 3: combine partial states across splits.
// ---------------------------------------------------------------------------
__global__ void __launch_bounds__(128) attn_combine_kernel(float* __restrict__ out) {
    const int tid = threadIdx.x;
    const int warp = tid >> 5, lane = tid & 31;
    const int row = blockIdx.x * 4 + warp;      // 0 .. BB*TT-1
    const int b = row / TT, t = row % TT;
    const int nS = t / CHUNK + 1;

    float M = -INFINITY, L = 0.f, acc = 0.f;
    const float2* pml2 = (const float2*)g_pml;
#pragma unroll 4
    for (int s2 = 0; s2 < nS; s2++) {
        const int pidx = (b * SPLITS + s2) * TT + t;
        float2 ml = pml2[pidx];
        if (ml.y == 0.0f) continue;            // split contributed nothing
        float os = g_po[pidx * DD + lane];
        if (ml.x > M) {
            float c = __expf(M - ml.x);
            L *= c; acc *= c; M = ml.x;
        }
        float w = __expf(ml.x - M);
        L   = fmaf(w, ml.y, L);
        acc = fmaf(w, os, acc);
    }
    out[row * DD + lane] = acc / L;
}

// ---------------------------------------------------------------------------
extern "C" void kernel_launch(void* const* d_in, const int* in_sizes, int n_in,
                              void* d_out, int out_size) {
    const float* x  = (const float*)d_in[0];
    const float* Wq = (const float*)d_in[1];
    const float* Wk = (const float*)d_in[2];
    const float* Wv = (const float*)d_in[3];
    float* out = (float*)d_out;

    qkv_kernel<<<(BB * TT) / 32, 128>>>(x, Wq, Wk, Wv);

    dim3 grid(TT / MTILE, SPLITS, BB);
    attn_partial_kernel<<<grid, 64>>>();

    attn_combine_kernel<<<(BB * TT) / 4, 128>>>(out);
}

// round 5
// speedup vs baseline: 1.7225x; 1.7225x over previous
#include <cuda_runtime.h>
#include <math.h>

#define BB 4
#define TT 4096
#define DD 32
#define SPLITS 8
#define CHUNK 512      // TT / SPLITS
#define MTILE 64       // query rows per CTA, 1 per thread (lean registers!)
#define NKEY 64        // key rows per smem tile

typedef unsigned long long u64;

// Scratch (no cudaMalloc allowed)
__device__ float g_q[BB * TT * DD];
__device__ float g_k[BB * TT * DD];
__device__ float g_v[BB * TT * DD];
__device__ float g_po[BB * SPLITS * TT * DD];   // partial o (unnormalized)
__device__ float g_pml[BB * SPLITS * TT * 2];   // partial (m, l)

// ---- packed f32x2 (Blackwell packed fp32 pipe; ptxas never emits from C++) ----
__device__ __forceinline__ u64 ffma2(u64 a, u64 b, u64 c) {
    u64 d; asm("fma.rn.f32x2 %0, %1, %2, %3;" : "=l"(d) : "l"(a), "l"(b), "l"(c)); return d;
}
__device__ __forceinline__ u64 fmul2(u64 a, u64 b) {
    u64 d; asm("mul.rn.f32x2 %0, %1, %2;" : "=l"(d) : "l"(a), "l"(b)); return d;
}
__device__ __forceinline__ u64 fadd2(u64 a, u64 b) {
    u64 d; asm("add.rn.f32x2 %0, %1, %2;" : "=l"(d) : "l"(a), "l"(b)); return d;
}
__device__ __forceinline__ u64 pack2(float lo, float hi) {
    u64 d; asm("mov.b64 %0, {%1, %2};" : "=l"(d) : "f"(lo), "f"(hi)); return d;
}
__device__ __forceinline__ float2 unpack2(u64 a) {
    float2 r; asm("mov.b64 {%0, %1}, %2;" : "=f"(r.x), "=f"(r.y) : "l"(a)); return r;
}

// ---------------------------------------------------------------------------
// Kernel 1: QKV projection. W rows in registers (thread -> h = lane),
// x staged in smem. 128 threads = 4 warps x 8 rows; grid = BB*TT/32.
// ---------------------------------------------------------------------------
__global__ void __launch_bounds__(128) qkv_kernel(const float* __restrict__ x,
                                                  const float* __restrict__ Wq,
                                                  const float* __restrict__ Wk,
                                                  const float* __restrict__ Wv) {
    __shared__ float4 xs[32 * 8];   // 32 rows x 32 floats = 4KB
    const int tid = threadIdx.x, lane = tid & 31, warp = tid >> 5;

    float wq[32], wk[32], wv[32];
    {
        const float4* Wq4 = (const float4*)(Wq + lane * DD);
        const float4* Wk4 = (const float4*)(Wk + lane * DD);
        const float4* Wv4 = (const float4*)(Wv + lane * DD);
#pragma unroll
        for (int j = 0; j < 8; j++) {
            ((float4*)wq)[j] = Wq4[j];
            ((float4*)wk)[j] = Wk4[j];
            ((float4*)wv)[j] = Wv4[j];
        }
    }
    const int rowbase = blockIdx.x * 32;
    const float4* xg = (const float4*)(x + rowbase * DD);
#pragma unroll
    for (int idx = tid; idx < 32 * 8; idx += 128) xs[idx] = xg[idx];
    __syncthreads();

#pragma unroll
    for (int rr = 0; rr < 8; rr++) {
        const int row = warp * 8 + rr;
        float aq = 0.f, ak = 0.f, av = 0.f;
#pragma unroll
        for (int j = 0; j < 8; j++) {
            float4 xv = xs[row * 8 + j];
            aq = fmaf(xv.x, wq[4*j],   aq); ak = fmaf(xv.x, wk[4*j],   ak); av = fmaf(xv.x, wv[4*j],   av);
            aq = fmaf(xv.y, wq[4*j+1], aq); ak = fmaf(xv.y, wk[4*j+1], ak); av = fmaf(xv.y, wv[4*j+1], av);
            aq = fmaf(xv.z, wq[4*j+2], aq); ak = fmaf(xv.z, wk[4*j+2], ak); av = fmaf(xv.z, wv[4*j+2], av);
            aq = fmaf(xv.w, wq[4*j+3], aq); ak = fmaf(xv.w, wk[4*j+3], ak); av = fmaf(xv.w, wv[4*j+3], av);
        }
        const int g = (rowbase + row) * DD + lane;
        g_q[g] = aq; g_k[g] = ak; g_v[g] = av;
    }
}

// ---------------------------------------------------------------------------
// Kernel 2: partial flash attention, split-KV, f32x2 packed math, 1 row/thread.
// grid = (TT/64, SPLITS, BB); 64 threads; thread -> query row.
// Register budget identical to the 239us baseline; FMA issue halved via FFMA2.
// ---------------------------------------------------------------------------
__global__ void __launch_bounds__(64) attn_partial_kernel() {
    const int i  = blockIdx.x;   // 64-row query tile
    const int sp = blockIdx.y;   // kv split
    const int b  = blockIdx.z;
    if (sp * 8 > i) return;      // chunk entirely above the diagonal

    const int tid = threadIdx.x;
    const int tq  = i * MTILE + tid;

    __shared__ ulonglong2 Ks[NKEY * 8];   // 64 rows x 128B = 8KB
    __shared__ ulonglong2 Vs[NKEY * 8];

    u64 q[16], o[16];
    {
        const u64 SC2 = pack2(0.17677669529663687f, 0.17677669529663687f);  // 32^-0.5
        const ulonglong2* qg = (const ulonglong2*)(g_q + (b * TT + tq) * DD);
#pragma unroll
        for (int j = 0; j < 8; j++) {
            ulonglong2 t = qg[j];
            q[2*j]   = fmul2(t.x, SC2);
            q[2*j+1] = fmul2(t.y, SC2);
        }
#pragma unroll
        for (int j = 0; j < 16; j++) o[j] = 0ull;
    }
    float m = -INFINITY, l = 0.f;

    const int nk = min(8, i - sp * 8 + 1);   // causal key tiles in this chunk
    const ulonglong2* Kg = (const ulonglong2*)(g_k + (b * TT + sp * CHUNK) * DD);
    const ulonglong2* Vg = (const ulonglong2*)(g_v + (b * TT + sp * CHUNK) * DD);

    for (int jt = 0; jt < nk; jt++) {
        if (jt) __syncthreads();
#pragma unroll
        for (int u = 0; u < 8; u++) {
            Ks[tid + 64 * u] = Kg[jt * 512 + tid + 64 * u];
            Vs[tid + 64 * u] = Vg[jt * 512 + tid + 64 * u];
        }
        __syncthreads();

        const int ktbase = sp * CHUNK + jt * NKEY;
        const int lim = min(NKEY, tq - ktbase + 1);   // >= 1 by construction
        for (int n = 0; n < lim; n++) {
            // QK dot: 16 FFMA2 into 2 packed accumulators (broadcast LDS)
            u64 a0 = 0ull, a1 = 0ull;
#pragma unroll
            for (int j = 0; j < 8; j++) {
                ulonglong2 kk = Ks[n * 8 + j];
                a0 = ffma2(q[2*j],   kk.x, a0);
                a1 = ffma2(q[2*j+1], kk.y, a1);
            }
            float2 s2 = unpack2(fadd2(a0, a1));
            const float sc = s2.x + s2.y;

            // Reference quirk: tril(wei)==0 -> -inf (causal + exact-zero).
            if (sc != 0.0f) {
                if (sc > m) {
                    float c = __expf(m - sc);   // exp(-inf)=0 covers first key
                    m = sc; l *= c;
                    u64 c2 = pack2(c, c);
#pragma unroll
                    for (int j = 0; j < 16; j++) o[j] = fmul2(o[j], c2);
                }
                float p = __expf(sc - m);
                l += p;
                u64 p2 = pack2(p, p);
#pragma unroll
                for (int j = 0; j < 8; j++) {
                    ulonglong2 vv = Vs[n * 8 + j];
                    o[2*j]   = ffma2(p2, vv.x, o[2*j]);
                    o[2*j+1] = ffma2(p2, vv.y, o[2*j+1]);
                }
            }
        }
    }

    const int pidx = (b * SPLITS + sp) * TT + tq;
    g_pml[2 * pidx]     = m;
    g_pml[2 * pidx + 1] = l;
    ulonglong2* po = (ulonglong2*)(g_po + pidx * DD);
#pragma unroll
    for (int j = 0; j < 8; j++) po[j] = make_ulonglong2(o[2*j], o[2*j+1]);
}

// ---------------------------------------------------------------------------
// Kernel 3: combine partial states across splits.
// ---------------------------------------------------------------------------
__global__ void __launch_bounds__(128) attn_combine_kernel(float* __restrict__ out) {
    const int tid = threadIdx.x;
    const int warp = tid >> 5, lane = tid & 31;
    const int row = blockIdx.x * 4 + warp;      // 0 .. BB*TT-1
    const int b = row / TT, t = row % TT;
    const int nS = t / CHUNK + 1;

    float M = -INFINITY, L = 0.f, acc = 0.f;
    const float2* pml2 = (const float2*)g_pml;
#pragma unroll 4
    for (int s2 = 0; s2 < nS; s2++) {
        const int pidx = (b * SPLITS + s2) * TT + t;
        float2 ml = pml2[pidx];
        if (ml.y == 0.0f) continue;            // split contributed nothing
        float os = g_po[pidx * DD + lane];
        if (ml.x > M) {
            float c = __expf(M - ml.x);
            L *= c; acc *= c; M = ml.x;
        }
        float w = __expf(ml.x - M);
        L   = fmaf(w, ml.y, L);
        acc = fmaf(w, os, acc);
    }
    out[row * DD + lane] = acc / L;
}

// ---------------------------------------------------------------------------
extern "C" void kernel_launch(void* const* d_in, const int* in_sizes, int n_in,
                              void* d_out, int out_size) {
    const float* x  = (const float*)d_in[0];
    const float* Wq = (const float*)d_in[1];
    const float* Wk = (const float*)d_in[2];
    const float* Wv = (const float*)d_in[3];
    float* out = (float*)d_out;

    qkv_kernel<<<(BB * TT) / 32, 128>>>(x, Wq, Wk, Wv);

    dim3 grid(TT / MTILE, SPLITS, BB);
    attn_partial_kernel<<<grid, 64>>>();

    attn_combine_kernel<<<(BB * TT) / 4, 128>>>(out);
}

// round 6
// speedup vs baseline: 1.7553x; 1.0190x over previous
#include <cuda_runtime.h>
#include <math.h>

#define BB 4
#define TT 4096
#define DD 32
#define SPLITS 8
#define CHUNK 512      // TT / SPLITS
#define MTILE 64       // query rows per CTA, 1 per thread
#define NKEY 64        // key rows per smem tile
#define KB 8           // keys per inner block (branch amortization)

typedef unsigned long long u64;

// Scratch (no cudaMalloc allowed)
__device__ float g_q[BB * TT * DD];
__device__ float g_k[BB * TT * DD];
__device__ float g_v[BB * TT * DD];
__device__ float g_po[BB * SPLITS * TT * DD];   // partial o (unnormalized)
__device__ float g_pml[BB * SPLITS * TT * 2];   // partial (m, l)

// ---- packed f32x2 helpers ----
__device__ __forceinline__ u64 ffma2(u64 a, u64 b, u64 c) {
    u64 d; asm("fma.rn.f32x2 %0, %1, %2, %3;" : "=l"(d) : "l"(a), "l"(b), "l"(c)); return d;
}
__device__ __forceinline__ u64 fmul2(u64 a, u64 b) {
    u64 d; asm("mul.rn.f32x2 %0, %1, %2;" : "=l"(d) : "l"(a), "l"(b)); return d;
}
__device__ __forceinline__ u64 fadd2(u64 a, u64 b) {
    u64 d; asm("add.rn.f32x2 %0, %1, %2;" : "=l"(d) : "l"(a), "l"(b)); return d;
}
__device__ __forceinline__ u64 pack2(float lo, float hi) {
    u64 d; asm("mov.b64 %0, {%1, %2};" : "=l"(d) : "f"(lo), "f"(hi)); return d;
}
__device__ __forceinline__ float2 unpack2(u64 a) {
    float2 r; asm("mov.b64 {%0, %1}, %2;" : "=f"(r.x), "=f"(r.y) : "l"(a)); return r;
}

// ---------------------------------------------------------------------------
// Kernel 1: QKV projection (unchanged from best).
// ---------------------------------------------------------------------------
__global__ void __launch_bounds__(128) qkv_kernel(const float* __restrict__ x,
                                                  const float* __restrict__ Wq,
                                                  const float* __restrict__ Wk,
                                                  const float* __restrict__ Wv) {
    __shared__ float4 xs[32 * 8];
    const int tid = threadIdx.x, lane = tid & 31, warp = tid >> 5;

    float wq[32], wk[32], wv[32];
    {
        const float4* Wq4 = (const float4*)(Wq + lane * DD);
        const float4* Wk4 = (const float4*)(Wk + lane * DD);
        const float4* Wv4 = (const float4*)(Wv + lane * DD);
#pragma unroll
        for (int j = 0; j < 8; j++) {
            ((float4*)wq)[j] = Wq4[j];
            ((float4*)wk)[j] = Wk4[j];
            ((float4*)wv)[j] = Wv4[j];
        }
    }
    const int rowbase = blockIdx.x * 32;
    const float4* xg = (const float4*)(x + rowbase * DD);
#pragma unroll
    for (int idx = tid; idx < 32 * 8; idx += 128) xs[idx] = xg[idx];
    __syncthreads();

#pragma unroll
    for (int rr = 0; rr < 8; rr++) {
        const int row = warp * 8 + rr;
        float aq = 0.f, ak = 0.f, av = 0.f;
#pragma unroll
        for (int j = 0; j < 8; j++) {
            float4 xv = xs[row * 8 + j];
            aq = fmaf(xv.x, wq[4*j],   aq); ak = fmaf(xv.x, wk[4*j],   ak); av = fmaf(xv.x, wv[4*j],   av);
            aq = fmaf(xv.y, wq[4*j+1], aq); ak = fmaf(xv.y, wk[4*j+1], ak); av = fmaf(xv.y, wv[4*j+1], av);
            aq = fmaf(xv.z, wq[4*j+2], aq); ak = fmaf(xv.z, wk[4*j+2], ak); av = fmaf(xv.z, wv[4*j+2], av);
            aq = fmaf(xv.w, wq[4*j+3], aq); ak = fmaf(xv.w, wk[4*j+3], ak); av = fmaf(xv.w, wv[4*j+3], av);
        }
        const int g = (rowbase + row) * DD + lane;
        g_q[g] = aq; g_k[g] = ak; g_v[g] = av;
    }
}

// ---------------------------------------------------------------------------
// Kernel 2: partial flash attention, split-KV, f32x2, 8-key blocks, branchless
// masking. grid = (TT/64, SPLITS, BB); 64 threads; thread -> query row.
// ---------------------------------------------------------------------------
__global__ void __launch_bounds__(64) attn_partial_kernel() {
    const int i  = blockIdx.x;   // 64-row query tile
    const int sp = blockIdx.y;   // kv split
    const int b  = blockIdx.z;
    if (sp * 8 > i) return;      // chunk entirely above the diagonal

    const int tid = threadIdx.x;
    const int tq  = i * MTILE + tid;
    const int warp_hi = i * MTILE + (tid & 32) + 31;   // lane31's row (warp-uniform)

    __shared__ ulonglong2 Ks[NKEY * 8];   // 64 rows x 128B = 8KB
    __shared__ ulonglong2 Vs[NKEY * 8];

    u64 q[16], o[16];
    {
        const u64 SC2 = pack2(0.17677669529663687f, 0.17677669529663687f);  // 32^-0.5
        const ulonglong2* qg = (const ulonglong2*)(g_q + (b * TT + tq) * DD);
#pragma unroll
        for (int j = 0; j < 8; j++) {
            ulonglong2 t = qg[j];
            q[2*j]   = fmul2(t.x, SC2);
            q[2*j+1] = fmul2(t.y, SC2);
        }
#pragma unroll
        for (int j = 0; j < 16; j++) o[j] = 0ull;
    }
    float m = -INFINITY, l = 0.f;

    const int nk = min(8, i - sp * 8 + 1);   // causal key tiles in this chunk
    const ulonglong2* Kg = (const ulonglong2*)(g_k + (b * TT + sp * CHUNK) * DD);
    const ulonglong2* Vg = (const ulonglong2*)(g_v + (b * TT + sp * CHUNK) * DD);

    for (int jt = 0; jt < nk; jt++) {
        if (jt) __syncthreads();
#pragma unroll
        for (int u = 0; u < 8; u++) {
            Ks[tid + 64 * u] = Kg[jt * 512 + tid + 64 * u];
            Vs[tid + 64 * u] = Vg[jt * 512 + tid + 64 * u];
        }
        __syncthreads();

        const int ktbase = sp * CHUNK + jt * NKEY;
        const int wlim = min(NKEY, warp_hi - ktbase + 1);   // warp-uniform trip

        for (int nb = 0; nb < wlim; nb += KB) {
            // --- 8 scores, branchless, 16 independent FFMA2 chains ---
            float s[KB];
#pragma unroll
            for (int u = 0; u < KB; u++) {
                const ulonglong2* kr = Ks + (nb + u) * 8;
                u64 a0 = 0ull, a1 = 0ull;
#pragma unroll
                for (int j = 0; j < 8; j++) {
                    ulonglong2 kk = kr[j];
                    a0 = ffma2(q[2*j],   kk.x, a0);
                    a1 = ffma2(q[2*j+1], kk.y, a1);
                }
                float2 s2 = unpack2(fadd2(a0, a1));
                float sc = s2.x + s2.y;
                // causal + reference tril-zero quirk, via select (no branch)
                bool valid = (ktbase + nb + u <= tq) && (sc != 0.0f);
                s[u] = valid ? sc : -INFINITY;
            }

            // --- one rescale decision per 8 keys ---
            float bm = s[0];
#pragma unroll
            for (int u = 1; u < KB; u++) bm = fmaxf(bm, s[u]);
            if (bm > m) {
                float c = __expf(m - bm);   // exp(-inf)=0 covers first block
                m = bm; l *= c;
                u64 c2 = pack2(c, c);
#pragma unroll
                for (int j = 0; j < 16; j++) o[j] = fmul2(o[j], c2);
            }

            // --- batched exp + unconditional PV accumulate ---
#pragma unroll
            for (int u = 0; u < KB; u++) {
                float p = __expf(s[u] - m);
                p = (s[u] == -INFINITY) ? 0.0f : p;   // kills -inf-(-inf)=NaN case
                l += p;
                u64 p2 = pack2(p, p);
                const ulonglong2* vr = Vs + (nb + u) * 8;
#pragma unroll
                for (int j = 0; j < 8; j++) {
                    ulonglong2 vv = vr[j];
                    o[2*j]   = ffma2(p2, vv.x, o[2*j]);
                    o[2*j+1] = ffma2(p2, vv.y, o[2*j+1]);
                }
            }
        }
    }

    const int pidx = (b * SPLITS + sp) * TT + tq;
    g_pml[2 * pidx]     = m;
    g_pml[2 * pidx + 1] = l;
    ulonglong2* po = (ulonglong2*)(g_po + pidx * DD);
#pragma unroll
    for (int j = 0; j < 8; j++) po[j] = make_ulonglong2(o[2*j], o[2*j+1]);
}

// ---------------------------------------------------------------------------
// Kernel 3: combine partial states across splits.
// ---------------------------------------------------------------------------
__global__ void __launch_bounds__(128) attn_combine_kernel(float* __restrict__ out) {
    const int tid = threadIdx.x;
    const int warp = tid >> 5, lane = tid & 31;
    const int row = blockIdx.x * 4 + warp;      // 0 .. BB*TT-1
    const int b = row / TT, t = row % TT;
    const int nS = t / CHUNK + 1;

    float M = -INFINITY, L = 0.f, acc = 0.f;
    const float2* pml2 = (const float2*)g_pml;
#pragma unroll 4
    for (int s2 = 0; s2 < nS; s2++) {
        const int pidx = (b * SPLITS + s2) * TT + t;
        float2 ml = pml2[pidx];
        if (ml.y == 0.0f) continue;            // split contributed nothing
        float os = g_po[pidx * DD + lane];
        if (ml.x > M) {
            float c = __expf(M - ml.x);
            L *= c; acc *= c; M = ml.x;
        }
        float w = __expf(ml.x - M);
        L   = fmaf(w, ml.y, L);
        acc = fmaf(w, os, acc);
    }
    out[row * DD + lane] = acc / L;
}

// ---------------------------------------------------------------------------
extern "C" void kernel_launch(void* const* d_in, const int* in_sizes, int n_in,
                              void* d_out, int out_size) {
    const float* x  = (const float*)d_in[0];
    const float* Wq = (const float*)d_in[1];
    const float* Wk = (const float*)d_in[2];
    const float* Wv = (const float*)d_in[3];
    float* out = (float*)d_out;

    qkv_kernel<<<(BB * TT) / 32, 128>>>(x, Wq, Wk, Wv);

    dim3 grid(TT / MTILE, SPLITS, BB);
    attn_partial_kernel<<<grid, 64>>>();

    attn_combine_kernel<<<(BB * TT) / 4, 128>>>(out);
}